// round 2
// baseline (speedup 1.0000x reference)
#include <cuda_runtime.h>
#include <cstdint>

// ============================================================================
// Gram matrix C = A^T A.  A: [8192, 4096] fp32 row-major. C: [4096, 4096] fp32.
// Target is effectively sm_100 base ISA (no tcgen05): Ampere-style
// mma.sync.m16n8k8 tf32 with ldmatrix, symmetric lower-triangle tiling.
// CTA tile 128(m) x 256(n), 8 warps of 64x64, BK=16, 2-stage smem pipeline.
// ============================================================================

#define NDIM 4096
#define KDIM 8192
#define BM 128
#define BN 256
#define BK 16
#define NCH (KDIM / BK)       // 512 k-chunks
#define THREADS 256
#define ROWB 80               // padded smem row: 20 floats (16 used) -> no bank conflicts

static constexpr int A_STAGE_B = BM * ROWB;            // 10240
static constexpr int B_STAGE_B = BN * ROWB;            // 20480
static constexpr int STAGE_B   = A_STAGE_B + B_STAGE_B; // 30720
static constexpr int SMEM_TOTAL = 2 * STAGE_B;          // 61440

__device__ __forceinline__ uint32_t smem_u32(const void* p) {
    uint32_t a;
    asm("{ .reg .u64 t; cvta.to.shared.u64 t, %1; cvt.u32.u64 %0, t; }"
        : "=r"(a) : "l"(p));
    return a;
}

__device__ __forceinline__ uint32_t f2tf32(float f) {
    uint32_t u;
    asm("cvt.rna.tf32.f32 %0, %1;" : "=r"(u) : "f"(f));
    return u;
}

__device__ __forceinline__ void ldsm4(uint32_t& r0, uint32_t& r1,
                                      uint32_t& r2, uint32_t& r3, uint32_t addr) {
    asm volatile("ldmatrix.sync.aligned.m8n8.x4.shared.b16 {%0,%1,%2,%3}, [%4];"
                 : "=r"(r0), "=r"(r1), "=r"(r2), "=r"(r3) : "r"(addr));
}

__device__ __forceinline__ void mma_tf32(float* c, const uint32_t* a, const uint32_t* b) {
    asm volatile(
        "mma.sync.aligned.m16n8k8.row.col.f32.tf32.tf32.f32 "
        "{%0,%1,%2,%3}, {%4,%5,%6,%7}, {%8,%9}, {%0,%1,%2,%3};"
        : "+f"(c[0]), "+f"(c[1]), "+f"(c[2]), "+f"(c[3])
        : "r"(a[0]), "r"(a[1]), "r"(a[2]), "r"(a[3]), "r"(b[0]), "r"(b[1]));
}

__global__ __launch_bounds__(THREADS, 1)
void gram_mma_kernel(const float* __restrict__ inp, float* __restrict__ out) {
    extern __shared__ char smem[];
    const uint32_t sbase = smem_u32(smem);
    const int tid  = threadIdx.x;
    const int lane = tid & 31;
    const int wid  = tid >> 5;
    const int wm   = wid >> 2;      // 0..1  (m position, 64 rows)
    const int wn   = wid & 3;       // 0..3  (n position, 64 cols)

    // -------- lower-triangle tile decode: keep (bi,bj) with bi >= 2*bj --------
    int t = (int)blockIdx.x, bj = 0;
    while (t >= 32 - 2 * bj) { t -= 32 - 2 * bj; ++bj; }
    const int bi = 2 * bj + t;
    const int i0 = bi * BM;         // C-row block == inp column block (A operand)
    const int j0 = bj * BN;         // C-col block == inp column block (B operand)

    // -------- per-thread ldmatrix address components --------
    const int g = lane >> 3, r8 = lane & 7;
    // A frag (m16 x k8): matrices [m0 k0][m8 k0][m0 k4][m8 k4]
    const int a_row = wm * 64 + ((g & 1) << 3) + r8;
    const int a_kb  = (g >> 1) << 4;
    // B frag x4 covers two n8 tiles: [n0 k0][n0 k4][n8 k0][n8 k4]
    const int b_row = wn * 64 + ((g >> 1) << 3) + r8;
    const int b_kb  = (g & 1) << 4;

    // -------- global-load task decode (fixed per thread) --------
    // A: 128 cols x 4 k-groups = 512 vec4 tasks (2/thread)
    // B: 256 cols x 4 k-groups = 1024 vec4 tasks (4/thread)
    int acol[2], akg[2], bcol[4], bkg[4];
#pragma unroll
    for (int s = 0; s < 2; ++s) { int a = tid + 256 * s; acol[s] = a & 127; akg[s] = a >> 7; }
#pragma unroll
    for (int s = 0; s < 4; ++s) { int b = tid + 256 * s; bcol[s] = b & 255; bkg[s] = b >> 8; }

    float acc[4][8][4];
#pragma unroll
    for (int i = 0; i < 4; ++i)
#pragma unroll
        for (int j = 0; j < 8; ++j)
#pragma unroll
            for (int q = 0; q < 4; ++q) acc[i][j][q] = 0.0f;

    // -------- prologue: load chunk 0 into stage 0 --------
    {
        const float* base = inp;  // k0 = 0
#pragma unroll
        for (int s = 0; s < 2; ++s) {
            const float* gp = base + (size_t)(akg[s] * 4) * NDIM + i0 + acol[s];
            uint32_t u0 = f2tf32(gp[0]);
            uint32_t u1 = f2tf32(gp[NDIM]);
            uint32_t u2 = f2tf32(gp[2 * NDIM]);
            uint32_t u3 = f2tf32(gp[3 * NDIM]);
            uint32_t ad = sbase + acol[s] * ROWB + (akg[s] << 4);
            asm volatile("st.shared.v4.b32 [%0], {%1,%2,%3,%4};"
                         :: "r"(ad), "r"(u0), "r"(u1), "r"(u2), "r"(u3) : "memory");
        }
#pragma unroll
        for (int s = 0; s < 4; ++s) {
            const float* gp = base + (size_t)(bkg[s] * 4) * NDIM + j0 + bcol[s];
            uint32_t u0 = f2tf32(gp[0]);
            uint32_t u1 = f2tf32(gp[NDIM]);
            uint32_t u2 = f2tf32(gp[2 * NDIM]);
            uint32_t u3 = f2tf32(gp[3 * NDIM]);
            uint32_t ad = sbase + A_STAGE_B + bcol[s] * ROWB + (bkg[s] << 4);
            asm volatile("st.shared.v4.b32 [%0], {%1,%2,%3,%4};"
                         :: "r"(ad), "r"(u0), "r"(u1), "r"(u2), "r"(u3) : "memory");
        }
    }
    __syncthreads();

    // -------- mainloop --------
    for (int c = 0; c < NCH; ++c) {
        const int cur = c & 1;
        const int nxt = cur ^ 1;

        // prefetch chunk c+1 from gmem into regs (long-latency, hidden by mma)
        float ra[2][4], rb[4][4];
        const bool more = (c + 1 < NCH);
        if (more) {
            const float* base = inp + (size_t)(c + 1) * BK * NDIM;
#pragma unroll
            for (int s = 0; s < 2; ++s) {
                const float* gp = base + (size_t)(akg[s] * 4) * NDIM + i0 + acol[s];
                ra[s][0] = gp[0]; ra[s][1] = gp[NDIM];
                ra[s][2] = gp[2 * NDIM]; ra[s][3] = gp[3 * NDIM];
            }
#pragma unroll
            for (int s = 0; s < 4; ++s) {
                const float* gp = base + (size_t)(bkg[s] * 4) * NDIM + j0 + bcol[s];
                rb[s][0] = gp[0]; rb[s][1] = gp[NDIM];
                rb[s][2] = gp[2 * NDIM]; rb[s][3] = gp[3 * NDIM];
            }
        }

        // MMA over stage cur
        const uint32_t As = sbase + cur * STAGE_B;
        const uint32_t Bs = As + A_STAGE_B;
#pragma unroll
        for (int ks = 0; ks < 2; ++ks) {
            uint32_t af[4][4];
#pragma unroll
            for (int i = 0; i < 4; ++i)
                ldsm4(af[i][0], af[i][1], af[i][2], af[i][3],
                      As + (uint32_t)(a_row + i * 16) * ROWB + (uint32_t)(ks * 32 + a_kb));
            uint32_t bf[8][2];
#pragma unroll
            for (int jj = 0; jj < 4; ++jj) {
                uint32_t r0, r1, r2, r3;
                ldsm4(r0, r1, r2, r3,
                      Bs + (uint32_t)(b_row + jj * 16) * ROWB + (uint32_t)(ks * 32 + b_kb));
                bf[2 * jj][0] = r0; bf[2 * jj][1] = r1;
                bf[2 * jj + 1][0] = r2; bf[2 * jj + 1][1] = r3;
            }
#pragma unroll
            for (int i = 0; i < 4; ++i)
#pragma unroll
                for (int j = 0; j < 8; ++j)
                    mma_tf32(acc[i][j], af[i], bf[j]);
        }
        __syncthreads();

        // STS prefetched chunk into stage nxt
        if (more) {
#pragma unroll
            for (int s = 0; s < 2; ++s) {
                uint32_t u0 = f2tf32(ra[s][0]), u1 = f2tf32(ra[s][1]);
                uint32_t u2 = f2tf32(ra[s][2]), u3 = f2tf32(ra[s][3]);
                uint32_t ad = sbase + nxt * STAGE_B + acol[s] * ROWB + (akg[s] << 4);
                asm volatile("st.shared.v4.b32 [%0], {%1,%2,%3,%4};"
                             :: "r"(ad), "r"(u0), "r"(u1), "r"(u2), "r"(u3) : "memory");
            }
#pragma unroll
            for (int s = 0; s < 4; ++s) {
                uint32_t u0 = f2tf32(rb[s][0]), u1 = f2tf32(rb[s][1]);
                uint32_t u2 = f2tf32(rb[s][2]), u3 = f2tf32(rb[s][3]);
                uint32_t ad = sbase + nxt * STAGE_B + A_STAGE_B + bcol[s] * ROWB + (bkg[s] << 4);
                asm volatile("st.shared.v4.b32 [%0], {%1,%2,%3,%4};"
                             :: "r"(ad), "r"(u0), "r"(u1), "r"(u2), "r"(u3) : "memory");
            }
            __syncthreads();
        }
    }

    // -------- epilogue: direct + mirrored (C symmetric) --------
    const int qrow = lane >> 2;
    const int qcol = (lane & 3) << 1;
#pragma unroll
    for (int i = 0; i < 4; ++i) {
        const int rm = i0 + wm * 64 + i * 16 + qrow;
#pragma unroll
        for (int j = 0; j < 8; ++j) {
            const int cn = j0 + wn * 64 + j * 8 + qcol;
            // direct: C[rm][cn..cn+1], C[rm+8][cn..cn+1]
            float2* p0 = reinterpret_cast<float2*>(out + (size_t)rm * NDIM + cn);
            float2* p1 = reinterpret_cast<float2*>(out + (size_t)(rm + 8) * NDIM + cn);
            *p0 = make_float2(acc[i][j][0], acc[i][j][1]);
            *p1 = make_float2(acc[i][j][2], acc[i][j][3]);
            // mirror: C[cn][rm], C[cn+1][rm], C[cn][rm+8], C[cn+1][rm+8]
            out[(size_t)cn * NDIM + rm]           = acc[i][j][0];
            out[(size_t)(cn + 1) * NDIM + rm]     = acc[i][j][1];
            out[(size_t)cn * NDIM + rm + 8]       = acc[i][j][2];
            out[(size_t)(cn + 1) * NDIM + rm + 8] = acc[i][j][3];
        }
    }
}

extern "C" void kernel_launch(void* const* d_in, const int* in_sizes, int n_in,
                              void* d_out, int out_size) {
    const float* inp = (const float*)d_in[0];
    float* out = (float*)d_out;
    cudaFuncSetAttribute(gram_mma_kernel,
                         cudaFuncAttributeMaxDynamicSharedMemorySize, SMEM_TOTAL);
    const int ntiles = 272;  // sum over bj<16 of (32 - 2*bj)
    gram_mma_kernel<<<ntiles, THREADS, SMEM_TOTAL>>>(inp, out);
}

// round 3
// speedup vs baseline: 1.0684x; 1.0684x over previous
#include <cuda_runtime.h>
#include <cstdint>

// ============================================================================
// Gram matrix C = A^T A.  A: [8192, 4096] fp32 row-major. C: [4096, 4096] fp32.
// Pass 1: transpose+convert A -> At (tf32, [4096][8192]) in __device__ scratch.
// Pass 2: GEMM C[i][j] = sum_k At[i][k] At[j][k] via mma.sync m16n8k8 tf32,
//         cp.async 3-stage pipeline, 128x256 CTA tile, lower-triangle grid.
// ============================================================================

#define NDIM 4096
#define KDIM 8192
#define BM 128
#define BN 256
#define BK 32
#define NCH (KDIM / BK)       // 256 k-chunks
#define THREADS 256
#define ROWB 144              // 32 floats + 16B pad: stride % 128B = 16 -> conflict-free
#define STAGES 3

static constexpr int A_STAGE_B = BM * ROWB;             // 18432
static constexpr int B_STAGE_B = BN * ROWB;             // 36864
static constexpr int STAGE_B   = A_STAGE_B + B_STAGE_B; // 55296
static constexpr int SMEM_TOTAL = STAGES * STAGE_B;     // 165888

__device__ uint32_t g_AT[(size_t)NDIM * KDIM];          // 128MB tf32 scratch

__device__ __forceinline__ uint32_t smem_u32(const void* p) {
    uint32_t a;
    asm("{ .reg .u64 t; cvta.to.shared.u64 t, %1; cvt.u32.u64 %0, t; }"
        : "=r"(a) : "l"(p));
    return a;
}

__device__ __forceinline__ uint32_t f2tf32(float f) {
    uint32_t u;
    asm("cvt.rna.tf32.f32 %0, %1;" : "=r"(u) : "f"(f));
    return u;
}

__device__ __forceinline__ void ldsm4(uint32_t& r0, uint32_t& r1,
                                      uint32_t& r2, uint32_t& r3, uint32_t addr) {
    asm volatile("ldmatrix.sync.aligned.m8n8.x4.shared.b16 {%0,%1,%2,%3}, [%4];"
                 : "=r"(r0), "=r"(r1), "=r"(r2), "=r"(r3) : "r"(addr));
}

__device__ __forceinline__ void mma_tf32(float* c, const uint32_t* a, const uint32_t* b) {
    asm volatile(
        "mma.sync.aligned.m16n8k8.row.col.f32.tf32.tf32.f32 "
        "{%0,%1,%2,%3}, {%4,%5,%6,%7}, {%8,%9}, {%0,%1,%2,%3};"
        : "+f"(c[0]), "+f"(c[1]), "+f"(c[2]), "+f"(c[3])
        : "r"(a[0]), "r"(a[1]), "r"(a[2]), "r"(a[3]), "r"(b[0]), "r"(b[1]));
}

__device__ __forceinline__ void cp16(uint32_t dst, const void* src) {
    asm volatile("cp.async.cg.shared.global [%0], [%1], 16;"
                 :: "r"(dst), "l"(src) : "memory");
}

// ---------------------------------------------------------------------------
// Pass 1: At[n][k] = tf32(inp[k][n]).  32x32 smem tiles, block (32,8).
// ---------------------------------------------------------------------------
__global__ __launch_bounds__(256) void transpose_cvt_kernel(
        const float* __restrict__ inp) {
    __shared__ float tile[32][33];
    const int tx = threadIdx.x, ty = threadIdx.y;
    const int n0 = blockIdx.x * 32;
    const int k0 = blockIdx.y * 32;
#pragma unroll
    for (int j = 0; j < 4; ++j)
        tile[ty + j * 8][tx] = inp[(size_t)(k0 + ty + j * 8) * NDIM + n0 + tx];
    __syncthreads();
#pragma unroll
    for (int j = 0; j < 4; ++j)
        g_AT[(size_t)(n0 + ty + j * 8) * KDIM + k0 + tx] =
            f2tf32(tile[tx][ty + j * 8]);
}

// ---------------------------------------------------------------------------
// Pass 2: GEMM
// ---------------------------------------------------------------------------
__global__ __launch_bounds__(THREADS, 1)
void gram_mma_kernel(float* __restrict__ out) {
    extern __shared__ char smem[];
    const uint32_t sbase = smem_u32(smem);
    const int tid  = threadIdx.x;
    const int lane = tid & 31;
    const int wid  = tid >> 5;
    const int wm   = wid >> 2;      // 0..1  (m position, 64 rows)
    const int wn   = wid & 3;       // 0..3  (n position, 64 cols)

    // lower-triangle tile decode: (bi,bj) with bi >= 2*bj on 32(m) x 16(n) grid
    int t = (int)blockIdx.x, bj = 0;
    while (t >= 32 - 2 * bj) { t -= 32 - 2 * bj; ++bj; }
    const int bi = 2 * bj + t;
    const int i0 = bi * BM;
    const int j0 = bj * BN;

    // ldmatrix address components (tf32 frag via b16 x4)
    const int g = lane >> 3, r8 = lane & 7;
    const int a_row = wm * 64 + ((g & 1) << 3) + r8;
    const uint32_t a_kb = (uint32_t)((g >> 1) << 4);
    const int b_row = wn * 64 + ((g >> 1) << 3) + r8;
    const uint32_t b_kb = (uint32_t)((g & 1) << 4);

    // cp.async task decode: A = 1024 chunks (128m x 8kg), B = 2048 (256m x 8kg)
    // 8 consecutive threads cover one 128B row segment -> coalesced.
    int am[4], ak[4];        // first 4 of 12 tasks are A, rest B
    int bm_[8], bk[8];
#pragma unroll
    for (int s = 0; s < 4; ++s) { int a = tid + 256 * s; am[s] = a >> 3; ak[s] = a & 7; }
#pragma unroll
    for (int s = 0; s < 8; ++s) { int b = tid + 256 * s; bm_[s] = b >> 3; bk[s] = b & 7; }

    const uint32_t* At = g_AT;

    auto issue_chunk = [&](int c) {
        const uint32_t st = sbase + (c % STAGES) * STAGE_B;
        const size_t kbase = (size_t)c * BK;
#pragma unroll
        for (int s = 0; s < 4; ++s)
            cp16(st + (uint32_t)(am[s] * ROWB + ak[s] * 16),
                 At + (size_t)(i0 + am[s]) * KDIM + kbase + ak[s] * 4);
        const uint32_t stB = st + A_STAGE_B;
#pragma unroll
        for (int s = 0; s < 8; ++s)
            cp16(stB + (uint32_t)(bm_[s] * ROWB + bk[s] * 16),
                 At + (size_t)(j0 + bm_[s]) * KDIM + kbase + bk[s] * 4);
        asm volatile("cp.async.commit_group;" ::: "memory");
    };

    float acc[4][8][4];
#pragma unroll
    for (int i = 0; i < 4; ++i)
#pragma unroll
        for (int j = 0; j < 8; ++j)
#pragma unroll
            for (int q = 0; q < 4; ++q) acc[i][j][q] = 0.0f;

    issue_chunk(0);
    issue_chunk(1);

    for (int c = 0; c < NCH; ++c) {
        if (c == NCH - 1)
            asm volatile("cp.async.wait_group 0;" ::: "memory");
        else
            asm volatile("cp.async.wait_group 1;" ::: "memory");
        __syncthreads();
        if (c + 2 < NCH) issue_chunk(c + 2);

        const uint32_t As = sbase + (c % STAGES) * STAGE_B;
        const uint32_t Bs = As + A_STAGE_B;
#pragma unroll
        for (int ks = 0; ks < 4; ++ks) {
            uint32_t af[4][4];
#pragma unroll
            for (int i = 0; i < 4; ++i)
                ldsm4(af[i][0], af[i][1], af[i][2], af[i][3],
                      As + (uint32_t)(a_row + i * 16) * ROWB + (uint32_t)(ks * 32) + a_kb);
            uint32_t bf[8][2];
#pragma unroll
            for (int jj = 0; jj < 4; ++jj) {
                uint32_t r0, r1, r2, r3;
                ldsm4(r0, r1, r2, r3,
                      Bs + (uint32_t)(b_row + jj * 16) * ROWB + (uint32_t)(ks * 32) + b_kb);
                bf[2 * jj][0] = r0; bf[2 * jj][1] = r1;
                bf[2 * jj + 1][0] = r2; bf[2 * jj + 1][1] = r3;
            }
#pragma unroll
            for (int i = 0; i < 4; ++i)
#pragma unroll
                for (int j = 0; j < 8; ++j)
                    mma_tf32(acc[i][j], af[i], bf[j]);
        }
        __syncthreads();
    }

    // epilogue: direct + mirrored (C symmetric)
    const int qrow = lane >> 2;
    const int qcol = (lane & 3) << 1;
#pragma unroll
    for (int i = 0; i < 4; ++i) {
        const int rm = i0 + wm * 64 + i * 16 + qrow;
#pragma unroll
        for (int j = 0; j < 8; ++j) {
            const int cn = j0 + wn * 64 + j * 8 + qcol;
            float2* p0 = reinterpret_cast<float2*>(out + (size_t)rm * NDIM + cn);
            float2* p1 = reinterpret_cast<float2*>(out + (size_t)(rm + 8) * NDIM + cn);
            *p0 = make_float2(acc[i][j][0], acc[i][j][1]);
            *p1 = make_float2(acc[i][j][2], acc[i][j][3]);
            out[(size_t)cn * NDIM + rm]           = acc[i][j][0];
            out[(size_t)(cn + 1) * NDIM + rm]     = acc[i][j][1];
            out[(size_t)cn * NDIM + rm + 8]       = acc[i][j][2];
            out[(size_t)(cn + 1) * NDIM + rm + 8] = acc[i][j][3];
        }
    }
}

extern "C" void kernel_launch(void* const* d_in, const int* in_sizes, int n_in,
                              void* d_out, int out_size) {
    const float* inp = (const float*)d_in[0];
    float* out = (float*)d_out;

    dim3 tgrid(NDIM / 32, KDIM / 32), tblk(32, 8);
    transpose_cvt_kernel<<<tgrid, tblk>>>(inp);

    cudaFuncSetAttribute(gram_mma_kernel,
                         cudaFuncAttributeMaxDynamicSharedMemorySize, SMEM_TOTAL);
    const int ntiles = 272;  // sum over bj<16 of (32 - 2*bj)
    gram_mma_kernel<<<ntiles, THREADS, SMEM_TOTAL>>>(out);
}

// round 5
// speedup vs baseline: 1.0823x; 1.0130x over previous
#include <cuda_runtime.h>
#include <cstdint>

// ============================================================================
// Gram matrix C = A^T A.  A: [8192, 4096] fp32 row-major. C: [4096, 4096] fp32.
// Pass 1: transpose+convert A -> At (tf32, [4096][8192]) in __device__ scratch.
// Pass 2: GEMM via mma.sync m16n8k8 tf32, cp.async 4-stage pipeline with ONE
//         __syncthreads per k-chunk, 128x256 CTA tile, lower-triangle grid.
// (Resubmission of Round-4 kernel: prior round died to broker infra, never ran.)
// ============================================================================

#define NDIM 4096
#define KDIM 8192
#define BM 128
#define BN 256
#define BK 32
#define NCH (KDIM / BK)       // 256 k-chunks
#define THREADS 256
#define ROWB 144              // 32 floats + 16B pad -> conflict-free LDSM/STS
#define STAGES 4

static constexpr int A_STAGE_B = BM * ROWB;             // 18432
static constexpr int B_STAGE_B = BN * ROWB;             // 36864
static constexpr int STAGE_B   = A_STAGE_B + B_STAGE_B; // 55296
static constexpr int SMEM_TOTAL = STAGES * STAGE_B;     // 221184

__device__ uint32_t g_AT[(size_t)NDIM * KDIM];          // 128MB tf32 scratch

__device__ __forceinline__ uint32_t smem_u32(const void* p) {
    uint32_t a;
    asm("{ .reg .u64 t; cvta.to.shared.u64 t, %1; cvt.u32.u64 %0, t; }"
        : "=r"(a) : "l"(p));
    return a;
}

__device__ __forceinline__ uint32_t f2tf32(float f) {
    uint32_t u;
    asm("cvt.rna.tf32.f32 %0, %1;" : "=r"(u) : "f"(f));
    return u;
}

__device__ __forceinline__ void ldsm4(uint32_t& r0, uint32_t& r1,
                                      uint32_t& r2, uint32_t& r3, uint32_t addr) {
    asm volatile("ldmatrix.sync.aligned.m8n8.x4.shared.b16 {%0,%1,%2,%3}, [%4];"
                 : "=r"(r0), "=r"(r1), "=r"(r2), "=r"(r3) : "r"(addr));
}

__device__ __forceinline__ void mma_tf32(float* c, const uint32_t* a, const uint32_t* b) {
    asm volatile(
        "mma.sync.aligned.m16n8k8.row.col.f32.tf32.tf32.f32 "
        "{%0,%1,%2,%3}, {%4,%5,%6,%7}, {%8,%9}, {%0,%1,%2,%3};"
        : "+f"(c[0]), "+f"(c[1]), "+f"(c[2]), "+f"(c[3])
        : "r"(a[0]), "r"(a[1]), "r"(a[2]), "r"(a[3]), "r"(b[0]), "r"(b[1]));
}

__device__ __forceinline__ void cp16(uint32_t dst, const void* src) {
    asm volatile("cp.async.cg.shared.global [%0], [%1], 16;"
                 :: "r"(dst), "l"(src) : "memory");
}

// ---------------------------------------------------------------------------
// Pass 1: At[n][k] = tf32(inp[k][n]).  32x32 smem tiles, block (32,8).
// ---------------------------------------------------------------------------
__global__ __launch_bounds__(256) void transpose_cvt_kernel(
        const float* __restrict__ inp) {
    __shared__ float tile[32][33];
    const int tx = threadIdx.x, ty = threadIdx.y;
    const int n0 = blockIdx.x * 32;
    const int k0 = blockIdx.y * 32;
#pragma unroll
    for (int j = 0; j < 4; ++j)
        tile[ty + j * 8][tx] = inp[(size_t)(k0 + ty + j * 8) * NDIM + n0 + tx];
    __syncthreads();
#pragma unroll
    for (int j = 0; j < 4; ++j)
        g_AT[(size_t)(n0 + ty + j * 8) * KDIM + k0 + tx] =
            f2tf32(tile[tx][ty + j * 8]);
}

// ---------------------------------------------------------------------------
// Pass 2: GEMM
// ---------------------------------------------------------------------------
__global__ __launch_bounds__(THREADS, 1)
void gram_mma_kernel(float* __restrict__ out) {
    extern __shared__ char smem[];
    const uint32_t sbase = smem_u32(smem);
    const int tid  = threadIdx.x;
    const int lane = tid & 31;
    const int wid  = tid >> 5;
    const int wm   = wid >> 2;      // 0..1  (m position, 64 rows)
    const int wn   = wid & 3;       // 0..3  (n position, 64 cols)

    // lower-triangle tile decode: (bi,bj) with bi >= 2*bj on 32(m) x 16(n) grid
    int t = (int)blockIdx.x, bj = 0;
    while (t >= 32 - 2 * bj) { t -= 32 - 2 * bj; ++bj; }
    const int bi = 2 * bj + t;
    const int i0 = bi * BM;
    const int j0 = bj * BN;

    // ldmatrix address components (tf32 frags via b16 x4)
    const int g = lane >> 3, r8 = lane & 7;
    const int a_row = wm * 64 + ((g & 1) << 3) + r8;
    const uint32_t a_kb = (uint32_t)((g >> 1) << 4);
    const int b_row = wn * 64 + ((g >> 1) << 3) + r8;
    const uint32_t b_kb = (uint32_t)((g & 1) << 4);

    // cp.async task decode: A = 1024 16B-chunks (128m x 8kg), B = 2048.
    // 8 consecutive threads cover one 128B k-segment -> coalesced.
    int am[4], ak[4];
    int bm_[8], bk[8];
#pragma unroll
    for (int s = 0; s < 4; ++s) { int a = tid + 256 * s; am[s] = a >> 3; ak[s] = a & 7; }
#pragma unroll
    for (int s = 0; s < 8; ++s) { int b = tid + 256 * s; bm_[s] = b >> 3; bk[s] = b & 7; }

    const uint32_t* At = g_AT;

    auto issue_chunk = [&](int c) {
        const uint32_t st = sbase + (c & (STAGES - 1)) * STAGE_B;
        const size_t kbase = (size_t)c * BK;
#pragma unroll
        for (int s = 0; s < 4; ++s)
            cp16(st + (uint32_t)(am[s] * ROWB + ak[s] * 16),
                 At + (size_t)(i0 + am[s]) * KDIM + kbase + ak[s] * 4);
        const uint32_t stB = st + A_STAGE_B;
#pragma unroll
        for (int s = 0; s < 8; ++s)
            cp16(stB + (uint32_t)(bm_[s] * ROWB + bk[s] * 16),
                 At + (size_t)(j0 + bm_[s]) * KDIM + kbase + bk[s] * 4);
        asm volatile("cp.async.commit_group;" ::: "memory");
    };

    float acc[4][8][4];
#pragma unroll
    for (int i = 0; i < 4; ++i)
#pragma unroll
        for (int j = 0; j < 8; ++j)
#pragma unroll
            for (int q = 0; q < 4; ++q) acc[i][j][q] = 0.0f;

    issue_chunk(0);
    issue_chunk(1);
    issue_chunk(2);

    for (int c = 0; c < NCH; ++c) {
        // guarantee group c complete (tail-exact clamp)
        if (c < NCH - 2)
            asm volatile("cp.async.wait_group 2;" ::: "memory");
        else if (c == NCH - 2)
            asm volatile("cp.async.wait_group 1;" ::: "memory");
        else
            asm volatile("cp.async.wait_group 0;" ::: "memory");
        __syncthreads();   // the ONLY barrier per chunk

        // stage (c+3)%4 == (c-1)%4: fully consumed before this barrier
        if (c + 3 < NCH) issue_chunk(c + 3);

        const uint32_t As = sbase + (c & (STAGES - 1)) * STAGE_B;
        const uint32_t Bs = As + A_STAGE_B;
#pragma unroll
        for (int ks = 0; ks < 4; ++ks) {
            uint32_t af[4][4];
#pragma unroll
            for (int i = 0; i < 4; ++i)
                ldsm4(af[i][0], af[i][1], af[i][2], af[i][3],
                      As + (uint32_t)(a_row + i * 16) * ROWB + (uint32_t)(ks * 32) + a_kb);
            uint32_t bf[8][2];
#pragma unroll
            for (int jj = 0; jj < 4; ++jj) {
                uint32_t r0, r1, r2, r3;
                ldsm4(r0, r1, r2, r3,
                      Bs + (uint32_t)(b_row + jj * 16) * ROWB + (uint32_t)(ks * 32) + b_kb);
                bf[2 * jj][0] = r0; bf[2 * jj][1] = r1;
                bf[2 * jj + 1][0] = r2; bf[2 * jj + 1][1] = r3;
            }
#pragma unroll
            for (int i = 0; i < 4; ++i)
#pragma unroll
                for (int j = 0; j < 8; ++j)
                    mma_tf32(acc[i][j], af[i], bf[j]);
        }
        // no trailing barrier: next iteration's sync provides the rendezvous
    }

    // epilogue: direct + mirrored (C symmetric)
    const int qrow = lane >> 2;
    const int qcol = (lane & 3) << 1;
#pragma unroll
    for (int i = 0; i < 4; ++i) {
        const int rm = i0 + wm * 64 + i * 16 + qrow;
#pragma unroll
        for (int j = 0; j < 8; ++j) {
            const int cn = j0 + wn * 64 + j * 8 + qcol;
            float2* p0 = reinterpret_cast<float2*>(out + (size_t)rm * NDIM + cn);
            float2* p1 = reinterpret_cast<float2*>(out + (size_t)(rm + 8) * NDIM + cn);
            *p0 = make_float2(acc[i][j][0], acc[i][j][1]);
            *p1 = make_float2(acc[i][j][2], acc[i][j][3]);
            out[(size_t)cn * NDIM + rm]           = acc[i][j][0];
            out[(size_t)(cn + 1) * NDIM + rm]     = acc[i][j][1];
            out[(size_t)cn * NDIM + rm + 8]       = acc[i][j][2];
            out[(size_t)(cn + 1) * NDIM + rm + 8] = acc[i][j][3];
        }
    }
}

extern "C" void kernel_launch(void* const* d_in, const int* in_sizes, int n_in,
                              void* d_out, int out_size) {
    const float* inp = (const float*)d_in[0];
    float* out = (float*)d_out;

    dim3 tgrid(NDIM / 32, KDIM / 32), tblk(32, 8);
    transpose_cvt_kernel<<<tgrid, tblk>>>(inp);

    cudaFuncSetAttribute(gram_mma_kernel,
                         cudaFuncAttributeMaxDynamicSharedMemorySize, SMEM_TOTAL);
    const int ntiles = 272;  // sum over bj<16 of (32 - 2*bj)
    gram_mma_kernel<<<ntiles, THREADS, SMEM_TOTAL>>>(out);
}

// round 8
// speedup vs baseline: 1.1170x; 1.0321x over previous
#include <cuda_runtime.h>
#include <cstdint>

// ============================================================================
// Gram matrix C = A^T A.  A: [8192, 4096] fp32 row-major. C: [4096, 4096] fp32.
// Pass 1: transpose+convert A -> At (tf32, [4096][8192]) in __device__ scratch.
// Pass 2: GEMM via mma.sync m16n8k8 tf32, cp.async 4-stage pipeline, ONE
//         __syncthreads per k-chunk, 128x256 CTA tile, lower-triangle grid.
// R6/R8: 512 threads / 16 warps (warp tile 64x32) -> 4 warps/SMSP for latency
//        hiding; acc 64 regs/thread.  (Resubmission: R7 died to broker infra.)
// ============================================================================

#define NDIM 4096
#define KDIM 8192
#define BM 128
#define BN 256
#define BK 32
#define NCH (KDIM / BK)       // 256 k-chunks
#define THREADS 512
#define ROWB 144              // 32 floats + 16B pad -> conflict-free LDSM/STS
#define STAGES 4

static constexpr int A_STAGE_B = BM * ROWB;             // 18432
static constexpr int B_STAGE_B = BN * ROWB;             // 36864
static constexpr int STAGE_B   = A_STAGE_B + B_STAGE_B; // 55296
static constexpr int SMEM_TOTAL = STAGES * STAGE_B;     // 221184

__device__ uint32_t g_AT[(size_t)NDIM * KDIM];          // 128MB tf32 scratch

__device__ __forceinline__ uint32_t smem_u32(const void* p) {
    uint32_t a;
    asm("{ .reg .u64 t; cvta.to.shared.u64 t, %1; cvt.u32.u64 %0, t; }"
        : "=r"(a) : "l"(p));
    return a;
}

__device__ __forceinline__ uint32_t f2tf32(float f) {
    uint32_t u;
    asm("cvt.rna.tf32.f32 %0, %1;" : "=r"(u) : "f"(f));
    return u;
}

__device__ __forceinline__ void ldsm4(uint32_t& r0, uint32_t& r1,
                                      uint32_t& r2, uint32_t& r3, uint32_t addr) {
    asm volatile("ldmatrix.sync.aligned.m8n8.x4.shared.b16 {%0,%1,%2,%3}, [%4];"
                 : "=r"(r0), "=r"(r1), "=r"(r2), "=r"(r3) : "r"(addr));
}

__device__ __forceinline__ void mma_tf32(float* c, const uint32_t* a, const uint32_t* b) {
    asm volatile(
        "mma.sync.aligned.m16n8k8.row.col.f32.tf32.tf32.f32 "
        "{%0,%1,%2,%3}, {%4,%5,%6,%7}, {%8,%9}, {%0,%1,%2,%3};"
        : "+f"(c[0]), "+f"(c[1]), "+f"(c[2]), "+f"(c[3])
        : "r"(a[0]), "r"(a[1]), "r"(a[2]), "r"(a[3]), "r"(b[0]), "r"(b[1]));
}

__device__ __forceinline__ void cp16(uint32_t dst, const void* src) {
    asm volatile("cp.async.cg.shared.global [%0], [%1], 16;"
                 :: "r"(dst), "l"(src) : "memory");
}

// ---------------------------------------------------------------------------
// Pass 1: At[n][k] = tf32(inp[k][n]).  32x32 smem tiles, block (32,8).
// ---------------------------------------------------------------------------
__global__ __launch_bounds__(256) void transpose_cvt_kernel(
        const float* __restrict__ inp) {
    __shared__ float tile[32][33];
    const int tx = threadIdx.x, ty = threadIdx.y;
    const int n0 = blockIdx.x * 32;
    const int k0 = blockIdx.y * 32;
#pragma unroll
    for (int j = 0; j < 4; ++j)
        tile[ty + j * 8][tx] = inp[(size_t)(k0 + ty + j * 8) * NDIM + n0 + tx];
    __syncthreads();
#pragma unroll
    for (int j = 0; j < 4; ++j)
        g_AT[(size_t)(n0 + ty + j * 8) * KDIM + k0 + tx] =
            f2tf32(tile[tx][ty + j * 8]);
}

// ---------------------------------------------------------------------------
// Pass 2: GEMM.  16 warps: wm = wid>>3 (2 x 64 rows), wn = wid&7 (8 x 32 cols)
// ---------------------------------------------------------------------------
__global__ __launch_bounds__(THREADS, 1)
void gram_mma_kernel(float* __restrict__ out) {
    extern __shared__ char smem[];
    const uint32_t sbase = smem_u32(smem);
    const int tid  = threadIdx.x;
    const int lane = tid & 31;
    const int wid  = tid >> 5;
    const int wm   = wid >> 3;      // 0..1  (m position, 64 rows)
    const int wn   = wid & 7;       // 0..7  (n position, 32 cols)

    // lower-triangle tile decode: (bi,bj) with bi >= 2*bj on 32(m) x 16(n) grid
    int t = (int)blockIdx.x, bj = 0;
    while (t >= 32 - 2 * bj) { t -= 32 - 2 * bj; ++bj; }
    const int bi = 2 * bj + t;
    const int i0 = bi * BM;
    const int j0 = bj * BN;

    // ldmatrix address components (tf32 frags via b16 x4)
    const int g = lane >> 3, r8 = lane & 7;
    const int a_row = wm * 64 + ((g & 1) << 3) + r8;
    const uint32_t a_kb = (uint32_t)((g >> 1) << 4);
    const int b_row = wn * 32 + ((g >> 1) << 3) + r8;
    const uint32_t b_kb = (uint32_t)((g & 1) << 4);

    // cp.async task decode: A = 1024 16B-chunks (128m x 8kg) -> 2/thread,
    // B = 2048 -> 4/thread.  8 consecutive threads cover one 128B k-segment.
    int am[2], ak[2];
    int bm_[4], bk[4];
#pragma unroll
    for (int s = 0; s < 2; ++s) { int a = tid + THREADS * s; am[s] = a >> 3; ak[s] = a & 7; }
#pragma unroll
    for (int s = 0; s < 4; ++s) { int b = tid + THREADS * s; bm_[s] = b >> 3; bk[s] = b & 7; }

    const uint32_t* At = g_AT;

    auto issue_chunk = [&](int c) {
        const uint32_t st = sbase + (c & (STAGES - 1)) * STAGE_B;
        const size_t kbase = (size_t)c * BK;
#pragma unroll
        for (int s = 0; s < 2; ++s)
            cp16(st + (uint32_t)(am[s] * ROWB + ak[s] * 16),
                 At + (size_t)(i0 + am[s]) * KDIM + kbase + ak[s] * 4);
        const uint32_t stB = st + A_STAGE_B;
#pragma unroll
        for (int s = 0; s < 4; ++s)
            cp16(stB + (uint32_t)(bm_[s] * ROWB + bk[s] * 16),
                 At + (size_t)(j0 + bm_[s]) * KDIM + kbase + bk[s] * 4);
        asm volatile("cp.async.commit_group;" ::: "memory");
    };

    float acc[4][4][4];
#pragma unroll
    for (int i = 0; i < 4; ++i)
#pragma unroll
        for (int j = 0; j < 4; ++j)
#pragma unroll
            for (int q = 0; q < 4; ++q) acc[i][j][q] = 0.0f;

    issue_chunk(0);
    issue_chunk(1);
    issue_chunk(2);

    for (int c = 0; c < NCH; ++c) {
        // guarantee group c complete (tail-exact clamp)
        if (c < NCH - 2)
            asm volatile("cp.async.wait_group 2;" ::: "memory");
        else if (c == NCH - 2)
            asm volatile("cp.async.wait_group 1;" ::: "memory");
        else
            asm volatile("cp.async.wait_group 0;" ::: "memory");
        __syncthreads();   // the ONLY barrier per chunk

        // stage (c+3)%4 == (c-1)%4: fully consumed before this barrier
        if (c + 3 < NCH) issue_chunk(c + 3);

        const uint32_t As = sbase + (c & (STAGES - 1)) * STAGE_B;
        const uint32_t Bs = As + A_STAGE_B;
#pragma unroll
        for (int ks = 0; ks < 4; ++ks) {
            uint32_t af[4][4];
#pragma unroll
            for (int i = 0; i < 4; ++i)
                ldsm4(af[i][0], af[i][1], af[i][2], af[i][3],
                      As + (uint32_t)(a_row + i * 16) * ROWB + (uint32_t)(ks * 32) + a_kb);
            uint32_t bf[4][2];
#pragma unroll
            for (int jj = 0; jj < 2; ++jj) {
                uint32_t r0, r1, r2, r3;
                ldsm4(r0, r1, r2, r3,
                      Bs + (uint32_t)(b_row + jj * 16) * ROWB + (uint32_t)(ks * 32) + b_kb);
                bf[2 * jj][0] = r0; bf[2 * jj][1] = r1;
                bf[2 * jj + 1][0] = r2; bf[2 * jj + 1][1] = r3;
            }
#pragma unroll
            for (int i = 0; i < 4; ++i)
#pragma unroll
                for (int j = 0; j < 4; ++j)
                    mma_tf32(acc[i][j], af[i], bf[j]);
        }
        // no trailing barrier: next iteration's sync provides the rendezvous
    }

    // epilogue: direct + mirrored (C symmetric)
    const int qrow = lane >> 2;
    const int qcol = (lane & 3) << 1;
#pragma unroll
    for (int i = 0; i < 4; ++i) {
        const int rm = i0 + wm * 64 + i * 16 + qrow;
#pragma unroll
        for (int j = 0; j < 4; ++j) {
            const int cn = j0 + wn * 32 + j * 8 + qcol;
            float2* p0 = reinterpret_cast<float2*>(out + (size_t)rm * NDIM + cn);
            float2* p1 = reinterpret_cast<float2*>(out + (size_t)(rm + 8) * NDIM + cn);
            *p0 = make_float2(acc[i][j][0], acc[i][j][1]);
            *p1 = make_float2(acc[i][j][2], acc[i][j][3]);
            out[(size_t)cn * NDIM + rm]           = acc[i][j][0];
            out[(size_t)(cn + 1) * NDIM + rm]     = acc[i][j][1];
            out[(size_t)cn * NDIM + rm + 8]       = acc[i][j][2];
            out[(size_t)(cn + 1) * NDIM + rm + 8] = acc[i][j][3];
        }
    }
}

extern "C" void kernel_launch(void* const* d_in, const int* in_sizes, int n_in,
                              void* d_out, int out_size) {
    const float* inp = (const float*)d_in[0];
    float* out = (float*)d_out;

    dim3 tgrid(NDIM / 32, KDIM / 32), tblk(32, 8);
    transpose_cvt_kernel<<<tgrid, tblk>>>(inp);

    cudaFuncSetAttribute(gram_mma_kernel,
                         cudaFuncAttributeMaxDynamicSharedMemorySize, SMEM_TOTAL);
    const int ntiles = 272;  // sum over bj<16 of (32 - 2*bj)
    gram_mma_kernel<<<ntiles, THREADS, SMEM_TOTAL>>>(out);
}